// round 4
// baseline (speedup 1.0000x reference)
#include <cuda_runtime.h>
#include <cstdint>

// Problem constants (fixed by the reference)
#define N_USERS   100000
#define N_ITEMS   200000
#define N_NODES   (N_USERS + N_ITEMS)     // 300000
#define DIM       64
#define NE        (N_NODES * DIM)         // 19,200,000 floats
#define NE4       (NE / 4)
#define NNZ_MAX   4000000
#define SCAN_BS   1024
#define SCAN_NBLK ((N_NODES + SCAN_BS - 1) / SCAN_BS)   // 293

// Static scratch
__device__ int   g_count[N_NODES];
__device__ int   g_rowstart[N_NODES];
__device__ int   g_cursor[N_NODES];
__device__ int   g_aux[512];
__device__ int2  g_cv[NNZ_MAX];          // {col, val_bits} in CSR order
__device__ float g_B1[NE];
__device__ float g_B2[NE];

// ---------------------------------------------------------------------------
// zero counters + cursors
// ---------------------------------------------------------------------------
__global__ void k_zero_cc(int* __restrict__ count, int* __restrict__ cursor) {
    int i = blockIdx.x * blockDim.x + threadIdx.x;
    if (i < N_NODES) { count[i] = 0; cursor[i] = 0; }
}

// ---------------------------------------------------------------------------
// histogram of row indices
// ---------------------------------------------------------------------------
__global__ void k_hist(const int* __restrict__ rows, int* __restrict__ count, int nnz) {
    int e = blockIdx.x * blockDim.x + threadIdx.x;
    if (e < nnz) atomicAdd(&count[__ldcs(rows + e)], 1);
}

// ---------------------------------------------------------------------------
// scan level 1: block-exclusive scan of count -> rowstart, block totals -> aux
// ---------------------------------------------------------------------------
__global__ void k_scan1(const int* __restrict__ count,
                        int* __restrict__ rowstart,
                        int* __restrict__ aux) {
    __shared__ int sh[SCAN_BS];
    int tid = threadIdx.x;
    int idx = blockIdx.x * SCAN_BS + tid;
    int v = (idx < N_NODES) ? count[idx] : 0;
    sh[tid] = v;
    __syncthreads();
    for (int off = 1; off < SCAN_BS; off <<= 1) {
        int t = (tid >= off) ? sh[tid - off] : 0;
        __syncthreads();
        sh[tid] += t;
        __syncthreads();
    }
    if (idx < N_NODES) rowstart[idx] = sh[tid] - v;   // exclusive
    if (tid == SCAN_BS - 1) aux[blockIdx.x] = sh[tid];
}

// ---------------------------------------------------------------------------
// scan level 2: exclusive scan of block totals (single block)
// ---------------------------------------------------------------------------
__global__ void k_scan2(int* __restrict__ aux) {
    __shared__ int sh[512];
    int tid = threadIdx.x;
    int v = (tid < SCAN_NBLK) ? aux[tid] : 0;
    sh[tid] = v;
    __syncthreads();
    for (int off = 1; off < 512; off <<= 1) {
        int t = (tid >= off) ? sh[tid - off] : 0;
        __syncthreads();
        sh[tid] += t;
        __syncthreads();
    }
    if (tid < SCAN_NBLK) aux[tid] = sh[tid] - v;      // exclusive
}

// ---------------------------------------------------------------------------
// scan level 3: add block offsets
// ---------------------------------------------------------------------------
__global__ void k_scan3(int* __restrict__ rowstart, const int* __restrict__ aux) {
    int idx = blockIdx.x * SCAN_BS + threadIdx.x;
    if (idx < N_NODES) rowstart[idx] += aux[blockIdx.x];
}

// ---------------------------------------------------------------------------
// placement: scatter edges into CSR slots
// ---------------------------------------------------------------------------
__global__ void k_place(const int*   __restrict__ rows,
                        const int*   __restrict__ cols,
                        const float* __restrict__ vals,
                        const int*   __restrict__ rowstart,
                        int*         __restrict__ cursor,
                        int2*        __restrict__ cv,
                        int nnz) {
    int e = blockIdx.x * blockDim.x + threadIdx.x;
    if (e >= nnz) return;
    int r = __ldcs(rows + e);
    int pos = rowstart[r] + atomicAdd(&cursor[r], 1);
    cv[pos] = make_int2(__ldcs(cols + e), __float_as_int(__ldcs(vals + e)));
}

// ---------------------------------------------------------------------------
// CSR SpMM: warp per row, 2 floats per lane, register accumulation.
// Layer 1: gather from split user/item inputs.
// ---------------------------------------------------------------------------
__global__ void k_spmm_l1(const int2* __restrict__ cv,
                          const int*  __restrict__ rowstart,
                          const int*  __restrict__ count,
                          const float* __restrict__ user_emb,
                          const float* __restrict__ item_emb,
                          float* __restrict__ y) {
    int w = (blockIdx.x * blockDim.x + threadIdx.x) >> 5;
    if (w >= N_NODES) return;
    int lane = threadIdx.x & 31;
    int j = lane * 2;
    int s = rowstart[w];
    int n = count[w];
    const int2* p = cv + s;

    float a0 = 0.f, a1 = 0.f;
    int i = 0;
    for (; i + 3 < n; i += 4) {
        int2 e0 = p[i], e1 = p[i+1], e2 = p[i+2], e3 = p[i+3];
        const float* s0 = (e0.x < N_USERS) ? user_emb + (size_t)e0.x * DIM : item_emb + (size_t)(e0.x - N_USERS) * DIM;
        const float* s1 = (e1.x < N_USERS) ? user_emb + (size_t)e1.x * DIM : item_emb + (size_t)(e1.x - N_USERS) * DIM;
        const float* s2 = (e2.x < N_USERS) ? user_emb + (size_t)e2.x * DIM : item_emb + (size_t)(e2.x - N_USERS) * DIM;
        const float* s3 = (e3.x < N_USERS) ? user_emb + (size_t)e3.x * DIM : item_emb + (size_t)(e3.x - N_USERS) * DIM;
        float2 x0 = *(const float2*)(s0 + j);
        float2 x1 = *(const float2*)(s1 + j);
        float2 x2 = *(const float2*)(s2 + j);
        float2 x3 = *(const float2*)(s3 + j);
        a0 = fmaf(__int_as_float(e0.y), x0.x, a0); a1 = fmaf(__int_as_float(e0.y), x0.y, a1);
        a0 = fmaf(__int_as_float(e1.y), x1.x, a0); a1 = fmaf(__int_as_float(e1.y), x1.y, a1);
        a0 = fmaf(__int_as_float(e2.y), x2.x, a0); a1 = fmaf(__int_as_float(e2.y), x2.y, a1);
        a0 = fmaf(__int_as_float(e3.y), x3.x, a0); a1 = fmaf(__int_as_float(e3.y), x3.y, a1);
    }
    for (; i < n; i++) {
        int2 e0 = p[i];
        const float* s0 = (e0.x < N_USERS) ? user_emb + (size_t)e0.x * DIM : item_emb + (size_t)(e0.x - N_USERS) * DIM;
        float2 x0 = *(const float2*)(s0 + j);
        a0 = fmaf(__int_as_float(e0.y), x0.x, a0); a1 = fmaf(__int_as_float(e0.y), x0.y, a1);
    }
    *(float2*)(y + (size_t)w * DIM + j) = make_float2(a0, a1);
}

// ---------------------------------------------------------------------------
// CSR SpMM: generic middle layer (x -> y)
// ---------------------------------------------------------------------------
__global__ void k_spmm(const int2* __restrict__ cv,
                       const int*  __restrict__ rowstart,
                       const int*  __restrict__ count,
                       const float* __restrict__ x,
                       float* __restrict__ y) {
    int w = (blockIdx.x * blockDim.x + threadIdx.x) >> 5;
    if (w >= N_NODES) return;
    int lane = threadIdx.x & 31;
    int j = lane * 2;
    int s = rowstart[w];
    int n = count[w];
    const int2* p = cv + s;

    float a0 = 0.f, a1 = 0.f;
    int i = 0;
    for (; i + 3 < n; i += 4) {
        int2 e0 = p[i], e1 = p[i+1], e2 = p[i+2], e3 = p[i+3];
        float2 x0 = *(const float2*)(x + (size_t)e0.x * DIM + j);
        float2 x1 = *(const float2*)(x + (size_t)e1.x * DIM + j);
        float2 x2 = *(const float2*)(x + (size_t)e2.x * DIM + j);
        float2 x3 = *(const float2*)(x + (size_t)e3.x * DIM + j);
        a0 = fmaf(__int_as_float(e0.y), x0.x, a0); a1 = fmaf(__int_as_float(e0.y), x0.y, a1);
        a0 = fmaf(__int_as_float(e1.y), x1.x, a0); a1 = fmaf(__int_as_float(e1.y), x1.y, a1);
        a0 = fmaf(__int_as_float(e2.y), x2.x, a0); a1 = fmaf(__int_as_float(e2.y), x2.y, a1);
        a0 = fmaf(__int_as_float(e3.y), x3.x, a0); a1 = fmaf(__int_as_float(e3.y), x3.y, a1);
    }
    for (; i < n; i++) {
        int2 e0 = p[i];
        float2 x0 = *(const float2*)(x + (size_t)e0.x * DIM + j);
        a0 = fmaf(__int_as_float(e0.y), x0.x, a0); a1 = fmaf(__int_as_float(e0.y), x0.y, a1);
    }
    *(float2*)(y + (size_t)w * DIM + j) = make_float2(a0, a1);
}

// ---------------------------------------------------------------------------
// CSR SpMM layer 3 fused with final average:
// out[w] = 0.25 * (emb[w] + B1[w] + B2[w] + (S@B2)[w])
// ---------------------------------------------------------------------------
__global__ void k_spmm_final(const int2* __restrict__ cv,
                             const int*  __restrict__ rowstart,
                             const int*  __restrict__ count,
                             const float* __restrict__ x,       // = B2
                             const float* __restrict__ b1,
                             const float* __restrict__ user_emb,
                             const float* __restrict__ item_emb,
                             float* __restrict__ out) {
    int w = (blockIdx.x * blockDim.x + threadIdx.x) >> 5;
    if (w >= N_NODES) return;
    int lane = threadIdx.x & 31;
    int j = lane * 2;
    int s = rowstart[w];
    int n = count[w];
    const int2* p = cv + s;

    float a0 = 0.f, a1 = 0.f;
    int i = 0;
    for (; i + 3 < n; i += 4) {
        int2 e0 = p[i], e1 = p[i+1], e2 = p[i+2], e3 = p[i+3];
        float2 x0 = *(const float2*)(x + (size_t)e0.x * DIM + j);
        float2 x1 = *(const float2*)(x + (size_t)e1.x * DIM + j);
        float2 x2 = *(const float2*)(x + (size_t)e2.x * DIM + j);
        float2 x3 = *(const float2*)(x + (size_t)e3.x * DIM + j);
        a0 = fmaf(__int_as_float(e0.y), x0.x, a0); a1 = fmaf(__int_as_float(e0.y), x0.y, a1);
        a0 = fmaf(__int_as_float(e1.y), x1.x, a0); a1 = fmaf(__int_as_float(e1.y), x1.y, a1);
        a0 = fmaf(__int_as_float(e2.y), x2.x, a0); a1 = fmaf(__int_as_float(e2.y), x2.y, a1);
        a0 = fmaf(__int_as_float(e3.y), x3.x, a0); a1 = fmaf(__int_as_float(e3.y), x3.y, a1);
    }
    for (; i < n; i++) {
        int2 e0 = p[i];
        float2 x0 = *(const float2*)(x + (size_t)e0.x * DIM + j);
        a0 = fmaf(__int_as_float(e0.y), x0.x, a0); a1 = fmaf(__int_as_float(e0.y), x0.y, a1);
    }

    size_t off = (size_t)w * DIM + j;
    float2 e = (w < N_USERS) ? *(const float2*)(user_emb + off)
                             : *(const float2*)(item_emb + off - (size_t)N_USERS * DIM);
    float2 v1 = *(const float2*)(b1 + off);
    float2 v2 = *(const float2*)(x + off);     // B2 itself
    float2 o;
    o.x = 0.25f * (e.x + v1.x + v2.x + a0);
    o.y = 0.25f * (e.y + v1.y + v2.y + a1);
    *(float2*)(out + off) = o;
}

// ---------------------------------------------------------------------------
// launch
// ---------------------------------------------------------------------------
extern "C" void kernel_launch(void* const* d_in, const int* in_sizes, int n_in,
                              void* d_out, int out_size) {
    const float* user_emb = (const float*)d_in[0];
    const float* item_emb = (const float*)d_in[1];
    const int*   e_rows   = (const int*)d_in[2];
    const int*   e_cols   = (const int*)d_in[3];
    const float* e_vals   = (const float*)d_in[4];
    float* out = (float*)d_out;
    const int nnz = in_sizes[2];

    int*   count;    cudaGetSymbolAddress((void**)&count,    g_count);
    int*   rowstart; cudaGetSymbolAddress((void**)&rowstart, g_rowstart);
    int*   cursor;   cudaGetSymbolAddress((void**)&cursor,   g_cursor);
    int*   aux;      cudaGetSymbolAddress((void**)&aux,      g_aux);
    int2*  cv;       cudaGetSymbolAddress((void**)&cv,       g_cv);
    float* B1;       cudaGetSymbolAddress((void**)&B1,       g_B1);
    float* B2;       cudaGetSymbolAddress((void**)&B2,       g_B2);

    const int TB = 256;
    const int node_blocks = (N_NODES + TB - 1) / TB;
    const int edge_blocks = (nnz + TB - 1) / TB;
    const int spmm_blocks = (N_NODES * 32 + TB - 1) / TB;   // warp per row

    // ---- build CSR ----
    k_zero_cc<<<node_blocks, TB>>>(count, cursor);
    k_hist<<<edge_blocks, TB>>>(e_rows, count, nnz);
    k_scan1<<<SCAN_NBLK, SCAN_BS>>>(count, rowstart, aux);
    k_scan2<<<1, 512>>>(aux);
    k_scan3<<<SCAN_NBLK, SCAN_BS>>>(rowstart, aux);
    k_place<<<edge_blocks, TB>>>(e_rows, e_cols, e_vals, rowstart, cursor, cv, nnz);

    // ---- 3 propagation layers ----
    k_spmm_l1<<<spmm_blocks, TB>>>(cv, rowstart, count, user_emb, item_emb, B1);
    k_spmm<<<spmm_blocks, TB>>>(cv, rowstart, count, B1, B2);
    k_spmm_final<<<spmm_blocks, TB>>>(cv, rowstart, count, B2, B1, user_emb, item_emb, out);
}

// round 5
// speedup vs baseline: 1.5142x; 1.5142x over previous
#include <cuda_runtime.h>
#include <cstdint>

// Problem constants (fixed by the reference)
#define N_USERS   100000
#define N_ITEMS   200000
#define N_NODES   (N_USERS + N_ITEMS)     // 300000
#define DIM       64
#define NE        (N_NODES * DIM)         // 19,200,000 floats
#define NNZ_MAX   4000000
#define SCAN_BS   1024
#define SCAN_NBLK ((N_NODES + SCAN_BS - 1) / SCAN_BS)   // 293

// Static scratch
__device__ int   g_count[N_NODES];
__device__ int   g_rowstart[N_NODES];
__device__ int   g_cursor[N_NODES];
__device__ int   g_aux[512];
__device__ int2  g_cv[NNZ_MAX];          // {col, val_bits} in CSR order
__device__ float g_B1[NE];
__device__ float g_B2[NE];

// ---------------------------------------------------------------------------
// zero counters
// ---------------------------------------------------------------------------
__global__ void k_zero(int* __restrict__ count) {
    int i = blockIdx.x * blockDim.x + threadIdx.x;
    if (i < N_NODES) count[i] = 0;
}

// ---------------------------------------------------------------------------
// histogram of row indices
// ---------------------------------------------------------------------------
__global__ void k_hist(const int* __restrict__ rows, int* __restrict__ count, int nnz) {
    int e = blockIdx.x * blockDim.x + threadIdx.x;
    if (e < nnz) atomicAdd(&count[__ldcs(rows + e)], 1);
}

// ---------------------------------------------------------------------------
// scan level 1: block-exclusive scan of count -> rowstart, block totals -> aux
// ---------------------------------------------------------------------------
__global__ void k_scan1(const int* __restrict__ count,
                        int* __restrict__ rowstart,
                        int* __restrict__ aux) {
    __shared__ int sh[SCAN_BS];
    int tid = threadIdx.x;
    int idx = blockIdx.x * SCAN_BS + tid;
    int v = (idx < N_NODES) ? count[idx] : 0;
    sh[tid] = v;
    __syncthreads();
    for (int off = 1; off < SCAN_BS; off <<= 1) {
        int t = (tid >= off) ? sh[tid - off] : 0;
        __syncthreads();
        sh[tid] += t;
        __syncthreads();
    }
    if (idx < N_NODES) rowstart[idx] = sh[tid] - v;   // exclusive
    if (tid == SCAN_BS - 1) aux[blockIdx.x] = sh[tid];
}

// ---------------------------------------------------------------------------
// scan level 2: exclusive scan of block totals (single block)
// ---------------------------------------------------------------------------
__global__ void k_scan2(int* __restrict__ aux) {
    __shared__ int sh[512];
    int tid = threadIdx.x;
    int v = (tid < SCAN_NBLK) ? aux[tid] : 0;
    sh[tid] = v;
    __syncthreads();
    for (int off = 1; off < 512; off <<= 1) {
        int t = (tid >= off) ? sh[tid - off] : 0;
        __syncthreads();
        sh[tid] += t;
        __syncthreads();
    }
    if (tid < SCAN_NBLK) aux[tid] = sh[tid] - v;      // exclusive
}

// ---------------------------------------------------------------------------
// scan level 3: add block offsets; also init cursor = rowstart
// ---------------------------------------------------------------------------
__global__ void k_scan3(int* __restrict__ rowstart, const int* __restrict__ aux,
                        int* __restrict__ cursor) {
    int idx = blockIdx.x * SCAN_BS + threadIdx.x;
    if (idx < N_NODES) {
        int v = rowstart[idx] + aux[blockIdx.x];
        rowstart[idx] = v;
        cursor[idx]   = v;
    }
}

// ---------------------------------------------------------------------------
// placement: scatter edges into CSR slots (cursor pre-initialized to rowstart)
// ---------------------------------------------------------------------------
__global__ void k_place(const int*   __restrict__ rows,
                        const int*   __restrict__ cols,
                        const float* __restrict__ vals,
                        int*         __restrict__ cursor,
                        int2*        __restrict__ cv,
                        int nnz) {
    int e = blockIdx.x * blockDim.x + threadIdx.x;
    if (e >= nnz) return;
    int r = __ldcs(rows + e);
    int pos = atomicAdd(&cursor[r], 1);
    cv[pos] = make_int2(__ldcs(cols + e), __float_as_int(__ldcs(vals + e)));
}

// ---------------------------------------------------------------------------
// CSR SpMM core: half-warp per row, float4 per lane (16 lanes x 4 = 64 dims).
// ---------------------------------------------------------------------------
__device__ __forceinline__ float4 spmm_row(const int2* __restrict__ p, int n,
                                           const float* __restrict__ x, int j) {
    float4 a = make_float4(0.f, 0.f, 0.f, 0.f);
    int i = 0;
    for (; i + 4 <= n; i += 4) {
        int2 e0 = p[i], e1 = p[i+1], e2 = p[i+2], e3 = p[i+3];
        float4 x0 = *(const float4*)(x + (size_t)e0.x * DIM + j);
        float4 x1 = *(const float4*)(x + (size_t)e1.x * DIM + j);
        float4 x2 = *(const float4*)(x + (size_t)e2.x * DIM + j);
        float4 x3 = *(const float4*)(x + (size_t)e3.x * DIM + j);
        float v0 = __int_as_float(e0.y), v1 = __int_as_float(e1.y);
        float v2 = __int_as_float(e2.y), v3 = __int_as_float(e3.y);
        a.x = fmaf(v0, x0.x, a.x); a.y = fmaf(v0, x0.y, a.y);
        a.z = fmaf(v0, x0.z, a.z); a.w = fmaf(v0, x0.w, a.w);
        a.x = fmaf(v1, x1.x, a.x); a.y = fmaf(v1, x1.y, a.y);
        a.z = fmaf(v1, x1.z, a.z); a.w = fmaf(v1, x1.w, a.w);
        a.x = fmaf(v2, x2.x, a.x); a.y = fmaf(v2, x2.y, a.y);
        a.z = fmaf(v2, x2.z, a.z); a.w = fmaf(v2, x2.w, a.w);
        a.x = fmaf(v3, x3.x, a.x); a.y = fmaf(v3, x3.y, a.y);
        a.z = fmaf(v3, x3.z, a.z); a.w = fmaf(v3, x3.w, a.w);
    }
    for (; i < n; i++) {
        int2 e0 = p[i];
        float4 x0 = *(const float4*)(x + (size_t)e0.x * DIM + j);
        float v0 = __int_as_float(e0.y);
        a.x = fmaf(v0, x0.x, a.x); a.y = fmaf(v0, x0.y, a.y);
        a.z = fmaf(v0, x0.z, a.z); a.w = fmaf(v0, x0.w, a.w);
    }
    return a;
}

// generic middle layer: y = S @ x
__global__ void k_spmm(const int2* __restrict__ cv,
                       const int*  __restrict__ rowstart,
                       const int*  __restrict__ count,
                       const float* __restrict__ x,
                       float* __restrict__ y) {
    int t = blockIdx.x * blockDim.x + threadIdx.x;
    int r = t >> 4;                      // half-warp per row
    if (r >= N_NODES) return;
    int j = (t & 15) * 4;
    int s = rowstart[r];
    int n = count[r];
    float4 a = spmm_row(cv + s, n, x, j);
    *(float4*)(y + (size_t)r * DIM + j) = a;
}

// layer 1: gather from split user/item inputs
__global__ void k_spmm_l1(const int2* __restrict__ cv,
                          const int*  __restrict__ rowstart,
                          const int*  __restrict__ count,
                          const float* __restrict__ user_emb,
                          const float* __restrict__ item_emb,
                          float* __restrict__ y) {
    int t = blockIdx.x * blockDim.x + threadIdx.x;
    int r = t >> 4;
    if (r >= N_NODES) return;
    int j = (t & 15) * 4;
    int s = rowstart[r];
    int n = count[r];
    const int2* p = cv + s;

    float4 a = make_float4(0.f, 0.f, 0.f, 0.f);
    for (int i = 0; i < n; i++) {
        int2 e0 = p[i];
        const float* src = (e0.x < N_USERS)
            ? user_emb + (size_t)e0.x * DIM
            : item_emb + (size_t)(e0.x - N_USERS) * DIM;
        float4 x0 = *(const float4*)(src + j);
        float v0 = __int_as_float(e0.y);
        a.x = fmaf(v0, x0.x, a.x); a.y = fmaf(v0, x0.y, a.y);
        a.z = fmaf(v0, x0.z, a.z); a.w = fmaf(v0, x0.w, a.w);
    }
    *(float4*)(y + (size_t)r * DIM + j) = a;
}

// layer 3 fused with final average: out = 0.25 * (emb + B1 + B2 + S@B2)
__global__ void k_spmm_final(const int2* __restrict__ cv,
                             const int*  __restrict__ rowstart,
                             const int*  __restrict__ count,
                             const float* __restrict__ x,      // = B2
                             const float* __restrict__ b1,
                             const float* __restrict__ user_emb,
                             const float* __restrict__ item_emb,
                             float* __restrict__ out) {
    int t = blockIdx.x * blockDim.x + threadIdx.x;
    int r = t >> 4;
    if (r >= N_NODES) return;
    int j = (t & 15) * 4;
    int s = rowstart[r];
    int n = count[r];
    float4 a = spmm_row(cv + s, n, x, j);

    size_t off = (size_t)r * DIM + j;
    float4 e = (r < N_USERS) ? *(const float4*)(user_emb + off)
                             : *(const float4*)(item_emb + off - (size_t)N_USERS * DIM);
    float4 v1 = *(const float4*)(b1 + off);
    float4 v2 = *(const float4*)(x + off);
    float4 o;
    o.x = 0.25f * (e.x + v1.x + v2.x + a.x);
    o.y = 0.25f * (e.y + v1.y + v2.y + a.y);
    o.z = 0.25f * (e.z + v1.z + v2.z + a.z);
    o.w = 0.25f * (e.w + v1.w + v2.w + a.w);
    *(float4*)(out + off) = o;
}

// ---------------------------------------------------------------------------
// launch
// ---------------------------------------------------------------------------
extern "C" void kernel_launch(void* const* d_in, const int* in_sizes, int n_in,
                              void* d_out, int out_size) {
    const float* user_emb = (const float*)d_in[0];
    const float* item_emb = (const float*)d_in[1];
    const int*   e_rows   = (const int*)d_in[2];
    const int*   e_cols   = (const int*)d_in[3];
    const float* e_vals   = (const float*)d_in[4];
    float* out = (float*)d_out;
    const int nnz = in_sizes[2];

    int*   count;    cudaGetSymbolAddress((void**)&count,    g_count);
    int*   rowstart; cudaGetSymbolAddress((void**)&rowstart, g_rowstart);
    int*   cursor;   cudaGetSymbolAddress((void**)&cursor,   g_cursor);
    int*   aux;      cudaGetSymbolAddress((void**)&aux,      g_aux);
    int2*  cv;       cudaGetSymbolAddress((void**)&cv,       g_cv);
    float* B1;       cudaGetSymbolAddress((void**)&B1,       g_B1);
    float* B2;       cudaGetSymbolAddress((void**)&B2,       g_B2);

    const int TB = 256;
    const int node_blocks = (N_NODES + TB - 1) / TB;
    const int edge_blocks = (nnz + TB - 1) / TB;
    const int spmm_blocks = (N_NODES * 16 + TB - 1) / TB;   // half-warp per row

    // ---- build CSR ----
    k_zero<<<node_blocks, TB>>>(count);
    k_hist<<<edge_blocks, TB>>>(e_rows, count, nnz);
    k_scan1<<<SCAN_NBLK, SCAN_BS>>>(count, rowstart, aux);
    k_scan2<<<1, 512>>>(aux);
    k_scan3<<<SCAN_NBLK, SCAN_BS>>>(rowstart, aux, cursor);
    k_place<<<edge_blocks, TB>>>(e_rows, e_cols, e_vals, cursor, cv, nnz);

    // ---- 3 propagation layers (layer 3 fused with final average) ----
    k_spmm_l1<<<spmm_blocks, TB>>>(cv, rowstart, count, user_emb, item_emb, B1);
    k_spmm<<<spmm_blocks, TB>>>(cv, rowstart, count, B1, B2);
    k_spmm_final<<<spmm_blocks, TB>>>(cv, rowstart, count, B2, B1, user_emb, item_emb, out);
}

// round 9
// speedup vs baseline: 1.8920x; 1.2495x over previous
#include <cuda_runtime.h>
#include <cuda_fp16.h>
#include <cstdint>

// Problem constants (fixed by the reference)
#define N_USERS   100000
#define N_ITEMS   200000
#define N_NODES   (N_USERS + N_ITEMS)     // 300000
#define DIM       64
#define NE        (N_NODES * DIM)         // 19,200,000 elems
#define NNZ_MAX   4000000
#define SCAN_BS   1024
#define SCAN_NBLK ((N_NODES + SCAN_BS - 1) / SCAN_BS)   // 293

// Static scratch
__device__ int    g_count[N_NODES];
__device__ int    g_rowstart[N_NODES];
__device__ int    g_cursor[N_NODES];
__device__ int    g_aux[512];
__device__ int2   g_cv[NNZ_MAX];         // {col, val_bits} in CSR order
__device__ __half g_X0[NE];              // fp16 copy of concat(user,item)  (38.4 MB)
__device__ __half g_B1[NE];              // fp16 layer-1 output
__device__ __half g_B2[NE];              // fp16 layer-2 output

// helpers (declared BEFORE any use)
__device__ __forceinline__ unsigned h2_as_u32(__half2 h) {
    return *reinterpret_cast<unsigned*>(&h);
}
__device__ __forceinline__ float2 u32_as_f2(unsigned u) {
    return __half22float2(*reinterpret_cast<__half2*>(&u));
}

// ---------------------------------------------------------------------------
// zero counters
// ---------------------------------------------------------------------------
__global__ void k_zero(int* __restrict__ count) {
    int i = blockIdx.x * blockDim.x + threadIdx.x;
    if (i < N_NODES) count[i] = 0;
}

// ---------------------------------------------------------------------------
// histogram of row indices
// ---------------------------------------------------------------------------
__global__ void k_hist(const int* __restrict__ rows, int* __restrict__ count, int nnz) {
    int e = blockIdx.x * blockDim.x + threadIdx.x;
    if (e < nnz) atomicAdd(&count[__ldcs(rows + e)], 1);
}

// ---------------------------------------------------------------------------
// scan level 1: block-exclusive scan of count -> rowstart, block totals -> aux
// ---------------------------------------------------------------------------
__global__ void k_scan1(const int* __restrict__ count,
                        int* __restrict__ rowstart,
                        int* __restrict__ aux) {
    __shared__ int sh[SCAN_BS];
    int tid = threadIdx.x;
    int idx = blockIdx.x * SCAN_BS + tid;
    int v = (idx < N_NODES) ? count[idx] : 0;
    sh[tid] = v;
    __syncthreads();
    for (int off = 1; off < SCAN_BS; off <<= 1) {
        int t = (tid >= off) ? sh[tid - off] : 0;
        __syncthreads();
        sh[tid] += t;
        __syncthreads();
    }
    if (idx < N_NODES) rowstart[idx] = sh[tid] - v;   // exclusive
    if (tid == SCAN_BS - 1) aux[blockIdx.x] = sh[tid];
}

// ---------------------------------------------------------------------------
// scan level 2: exclusive scan of block totals (single block)
// ---------------------------------------------------------------------------
__global__ void k_scan2(int* __restrict__ aux) {
    __shared__ int sh[512];
    int tid = threadIdx.x;
    int v = (tid < SCAN_NBLK) ? aux[tid] : 0;
    sh[tid] = v;
    __syncthreads();
    for (int off = 1; off < 512; off <<= 1) {
        int t = (tid >= off) ? sh[tid - off] : 0;
        __syncthreads();
        sh[tid] += t;
        __syncthreads();
    }
    if (tid < SCAN_NBLK) aux[tid] = sh[tid] - v;      // exclusive
}

// ---------------------------------------------------------------------------
// scan level 3: add block offsets; also init cursor = rowstart
// ---------------------------------------------------------------------------
__global__ void k_scan3(int* __restrict__ rowstart, const int* __restrict__ aux,
                        int* __restrict__ cursor) {
    int idx = blockIdx.x * SCAN_BS + threadIdx.x;
    if (idx < N_NODES) {
        int v = rowstart[idx] + aux[blockIdx.x];
        rowstart[idx] = v;
        cursor[idx]   = v;
    }
}

// ---------------------------------------------------------------------------
// placement: scatter edges into CSR slots (cursor pre-initialized to rowstart)
// ---------------------------------------------------------------------------
__global__ void k_place(const int*   __restrict__ rows,
                        const int*   __restrict__ cols,
                        const float* __restrict__ vals,
                        int*         __restrict__ cursor,
                        int2*        __restrict__ cv,
                        int nnz) {
    int e = blockIdx.x * blockDim.x + threadIdx.x;
    if (e >= nnz) return;
    int r = __ldcs(rows + e);
    int pos = atomicAdd(&cursor[r], 1);
    cv[pos] = make_int2(__ldcs(cols + e), __float_as_int(__ldcs(vals + e)));
}

// ---------------------------------------------------------------------------
// convert: X0h = fp16(concat(user_emb, item_emb))
// thread handles 4 floats -> one uint2 (4 halves)
// ---------------------------------------------------------------------------
__global__ void k_convert(const float4* __restrict__ user_emb,
                          const float4* __restrict__ item_emb,
                          uint2* __restrict__ xh) {
    int i = blockIdx.x * blockDim.x + threadIdx.x;
    if (i >= NE / 4) return;
    const int U4 = N_USERS * DIM / 4;
    float4 v = (i < U4) ? user_emb[i] : item_emb[i - U4];
    uint2 o;
    o.x = h2_as_u32(__floats2half2_rn(v.x, v.y));
    o.y = h2_as_u32(__floats2half2_rn(v.z, v.w));
    xh[i] = o;
}

// ---------------------------------------------------------------------------
// CSR SpMM row core (fp16 gather, fp32 accumulate): half-warp per row,
// lane covers 4 dims (one uint2 = 4 halves per edge).
// ---------------------------------------------------------------------------
__device__ __forceinline__ float4 spmm_row_h(const int2* __restrict__ p, int n,
                                             const __half* __restrict__ x, int j) {
    float4 a = make_float4(0.f, 0.f, 0.f, 0.f);
    int i = 0;
    for (; i + 4 <= n; i += 4) {
        int2 e0 = p[i], e1 = p[i+1], e2 = p[i+2], e3 = p[i+3];
        uint2 r0 = *(const uint2*)(x + (size_t)e0.x * DIM + j);
        uint2 r1 = *(const uint2*)(x + (size_t)e1.x * DIM + j);
        uint2 r2 = *(const uint2*)(x + (size_t)e2.x * DIM + j);
        uint2 r3 = *(const uint2*)(x + (size_t)e3.x * DIM + j);
        float v0 = __int_as_float(e0.y), v1 = __int_as_float(e1.y);
        float v2 = __int_as_float(e2.y), v3 = __int_as_float(e3.y);
        {
            float2 f0 = u32_as_f2(r0.x), f1 = u32_as_f2(r0.y);
            a.x = fmaf(v0, f0.x, a.x); a.y = fmaf(v0, f0.y, a.y);
            a.z = fmaf(v0, f1.x, a.z); a.w = fmaf(v0, f1.y, a.w);
        }
        {
            float2 f0 = u32_as_f2(r1.x), f1 = u32_as_f2(r1.y);
            a.x = fmaf(v1, f0.x, a.x); a.y = fmaf(v1, f0.y, a.y);
            a.z = fmaf(v1, f1.x, a.z); a.w = fmaf(v1, f1.y, a.w);
        }
        {
            float2 f0 = u32_as_f2(r2.x), f1 = u32_as_f2(r2.y);
            a.x = fmaf(v2, f0.x, a.x); a.y = fmaf(v2, f0.y, a.y);
            a.z = fmaf(v2, f1.x, a.z); a.w = fmaf(v2, f1.y, a.w);
        }
        {
            float2 f0 = u32_as_f2(r3.x), f1 = u32_as_f2(r3.y);
            a.x = fmaf(v3, f0.x, a.x); a.y = fmaf(v3, f0.y, a.y);
            a.z = fmaf(v3, f1.x, a.z); a.w = fmaf(v3, f1.y, a.w);
        }
    }
    for (; i < n; i++) {
        int2 e0 = p[i];
        uint2 r0 = *(const uint2*)(x + (size_t)e0.x * DIM + j);
        float v0 = __int_as_float(e0.y);
        float2 f0 = u32_as_f2(r0.x), f1 = u32_as_f2(r0.y);
        a.x = fmaf(v0, f0.x, a.x); a.y = fmaf(v0, f0.y, a.y);
        a.z = fmaf(v0, f1.x, a.z); a.w = fmaf(v0, f1.y, a.w);
    }
    return a;
}

// generic layer: y_h = S @ x_h   (fp16 in, fp16 out)
__global__ void k_spmm_h(const int2* __restrict__ cv,
                         const int*  __restrict__ rowstart,
                         const int*  __restrict__ count,
                         const __half* __restrict__ x,
                         __half* __restrict__ y) {
    int t = blockIdx.x * blockDim.x + threadIdx.x;
    int r = t >> 4;                      // half-warp per row
    if (r >= N_NODES) return;
    int j = (t & 15) * 4;
    float4 a = spmm_row_h(cv + rowstart[r], count[r], x, j);
    uint2 o;
    o.x = h2_as_u32(__floats2half2_rn(a.x, a.y));
    o.y = h2_as_u32(__floats2half2_rn(a.z, a.w));
    *(uint2*)(y + (size_t)r * DIM + j) = o;
}

// layer 3 fused with final average: out = 0.25 * (emb + B1 + B2 + S@B2)
__global__ void k_spmm_final(const int2* __restrict__ cv,
                             const int*  __restrict__ rowstart,
                             const int*  __restrict__ count,
                             const __half* __restrict__ x,     // = B2 (fp16)
                             const __half* __restrict__ b1,    // = B1 (fp16)
                             const float* __restrict__ user_emb,
                             const float* __restrict__ item_emb,
                             float* __restrict__ out) {
    int t = blockIdx.x * blockDim.x + threadIdx.x;
    int r = t >> 4;
    if (r >= N_NODES) return;
    int j = (t & 15) * 4;
    float4 a = spmm_row_h(cv + rowstart[r], count[r], x, j);

    size_t off = (size_t)r * DIM + j;
    float4 e = (r < N_USERS) ? *(const float4*)(user_emb + off)
                             : *(const float4*)(item_emb + off - (size_t)N_USERS * DIM);
    uint2 rb1 = *(const uint2*)(b1 + off);
    uint2 rb2 = *(const uint2*)(x + off);
    float2 b1a = u32_as_f2(rb1.x), b1b = u32_as_f2(rb1.y);
    float2 b2a = u32_as_f2(rb2.x), b2b = u32_as_f2(rb2.y);

    float4 o;
    o.x = 0.25f * (e.x + b1a.x + b2a.x + a.x);
    o.y = 0.25f * (e.y + b1a.y + b2a.y + a.y);
    o.z = 0.25f * (e.z + b1b.x + b2b.x + a.z);
    o.w = 0.25f * (e.w + b1b.y + b2b.y + a.w);
    *(float4*)(out + off) = o;
}

// ---------------------------------------------------------------------------
// launch
// ---------------------------------------------------------------------------
extern "C" void kernel_launch(void* const* d_in, const int* in_sizes, int n_in,
                              void* d_out, int out_size) {
    const float* user_emb = (const float*)d_in[0];
    const float* item_emb = (const float*)d_in[1];
    const int*   e_rows   = (const int*)d_in[2];
    const int*   e_cols   = (const int*)d_in[3];
    const float* e_vals   = (const float*)d_in[4];
    float* out = (float*)d_out;
    const int nnz = in_sizes[2];

    int*    count;    cudaGetSymbolAddress((void**)&count,    g_count);
    int*    rowstart; cudaGetSymbolAddress((void**)&rowstart, g_rowstart);
    int*    cursor;   cudaGetSymbolAddress((void**)&cursor,   g_cursor);
    int*    aux;      cudaGetSymbolAddress((void**)&aux,      g_aux);
    int2*   cv;       cudaGetSymbolAddress((void**)&cv,       g_cv);
    __half* X0;       cudaGetSymbolAddress((void**)&X0,       g_X0);
    __half* B1;       cudaGetSymbolAddress((void**)&B1,       g_B1);
    __half* B2;       cudaGetSymbolAddress((void**)&B2,       g_B2);

    const int TB = 256;
    const int node_blocks = (N_NODES + TB - 1) / TB;
    const int edge_blocks = (nnz + TB - 1) / TB;
    const int conv_blocks = (NE / 4 + TB - 1) / TB;
    const int spmm_blocks = (N_NODES * 16 + TB - 1) / TB;   // half-warp per row

    // ---- build CSR + fp16 table ----
    k_zero<<<node_blocks, TB>>>(count);
    k_hist<<<edge_blocks, TB>>>(e_rows, count, nnz);
    k_scan1<<<SCAN_NBLK, SCAN_BS>>>(count, rowstart, aux);
    k_scan2<<<1, 512>>>(aux);
    k_scan3<<<SCAN_NBLK, SCAN_BS>>>(rowstart, aux, cursor);
    k_place<<<edge_blocks, TB>>>(e_rows, e_cols, e_vals, cursor, cv, nnz);
    k_convert<<<conv_blocks, TB>>>((const float4*)user_emb, (const float4*)item_emb,
                                   (uint2*)X0);

    // ---- 3 propagation layers (layer 3 fused with final average) ----
    k_spmm_h<<<spmm_blocks, TB>>>(cv, rowstart, count, X0, B1);
    k_spmm_h<<<spmm_blocks, TB>>>(cv, rowstart, count, B1, B2);
    k_spmm_final<<<spmm_blocks, TB>>>(cv, rowstart, count, B2, B1,
                                      user_emb, item_emb, out);
}